// round 2
// baseline (speedup 1.0000x reference)
#include <cuda_runtime.h>

// Problem constants
#define BB   16
#define CIN  64
#define COUT 64
#define HH   128
#define WW   128
#define NKW  (COUT * CIN * 9)   // 36864
#define AWN  (NKW + COUT)       // 36928

// Conv tiling: 16 rows x 32 cols spatial tile, 16 co per block, ci chunks of 8
#define TROW  16
#define TCOL  32
#define CICH  8
#define COG   16
#define XPAD  35   // odd stride -> conflict-free scalar LDS (3r+8q bank permutation)

// Scratch (allocation-free rule: __device__ globals)
__device__ float g_h[BB * 30];
__device__ float g_aw[BB * AWN];

// ---------------- packed f32x2 helpers (FFMA2 path) ------------------------
__device__ __forceinline__ unsigned long long pk2(float lo, float hi) {
    unsigned long long r;
    asm("mov.b64 %0, {%1,%2};" : "=l"(r) : "f"(lo), "f"(hi));
    return r;
}
__device__ __forceinline__ void ffma2(unsigned long long& acc,
                                      unsigned long long a,
                                      unsigned long long b) {
    asm("fma.rn.f32x2 %0, %1, %2, %0;" : "+l"(acc) : "l"(a), "l"(b));
}
__device__ __forceinline__ void upk2(unsigned long long v, float& lo, float& hi) {
    asm("mov.b64 {%0,%1}, %2;" : "=f"(lo), "=f"(hi) : "l"(v));
}

// ---------------------------------------------------------------------------
// MLP stage 1: h = relu(relu(z@W0^T + b0) @ W1^T + b1)   (per batch sample)
// ---------------------------------------------------------------------------
__global__ void mlp_h_kernel(const float* __restrict__ z,
                             const float* __restrict__ W0,
                             const float* __restrict__ b0,
                             const float* __restrict__ W1,
                             const float* __restrict__ b1) {
    const int b = blockIdx.x;
    const int t = threadIdx.x;
    __shared__ float h0[20];
    if (t < 20) {
        float s = b0[t];
        #pragma unroll
        for (int j = 0; j < 16; ++j) s += z[b * 16 + j] * W0[t * 16 + j];
        h0[t] = fmaxf(s, 0.0f);
    }
    __syncthreads();
    if (t < 30) {
        float s = b1[t];
        #pragma unroll
        for (int j = 0; j < 20; ++j) s += h0[j] * W1[t * 20 + j];
        g_h[b * 30 + t] = fmaxf(s, 0.0f);
    }
}

// ---------------------------------------------------------------------------
// MLP stage 2: aw[b, i] = relu(h[b] . W2[i] + b2[i])
// ---------------------------------------------------------------------------
__global__ __launch_bounds__(256) void mlp_aw_kernel(const float* __restrict__ W2,
                                                     const float* __restrict__ b2) {
    __shared__ float sh[BB * 30];
    const int tid = threadIdx.x;
    for (int j = tid; j < BB * 30; j += 256) sh[j] = g_h[j];
    __syncthreads();

    const int i = blockIdx.x * 256 + tid;
    if (i >= AWN) return;

    float w[30];
    #pragma unroll
    for (int j = 0; j < 30; ++j) w[j] = W2[i * 30 + j];
    const float bias = b2[i];

    #pragma unroll
    for (int b = 0; b < BB; ++b) {
        float s = bias;
        #pragma unroll
        for (int j = 0; j < 30; ++j) s += sh[b * 30 + j] * w[j];
        g_aw[b * AWN + i] = fmaxf(s, 0.0f);
    }
}

// ---------------------------------------------------------------------------
// Adaptive 3x3 SAME conv + bias + relu, packed f32x2 (FFMA2) inner loop.
// Grid: (32 tiles [8y x 4x], 4 co-groups, 16 batch). Block: 256 threads.
// Per thread: 4 co x 8 px (4 f32x2 accumulator pairs per co).
// ---------------------------------------------------------------------------
__global__ __launch_bounds__(256) void conv_kernel(const float* __restrict__ x,
                                                   float* __restrict__ out) {
    __shared__ float  sx[CICH][TROW + 2][XPAD];     // 8 ci x 18 x 35(pad)
    __shared__ float2 sw2[COG][CICH][9];            // weights pre-duplicated (w,w)

    const int tid  = threadIdx.x;
    const int tile = blockIdx.x;             // 0..31
    const int cog  = blockIdx.y;             // 0..3 (16 co each)
    const int b    = blockIdx.z;             // 0..15

    const int tx = (tile & 3) * TCOL;        // 0,32,64,96
    const int ty = (tile >> 2) * TROW;       // 0..112

    // thread -> (row, 8-px group, co sub-group)
    const int qid = tid & 63;
    const int row = qid >> 2;                // 0..15
    const int qx  = (qid & 3) * 8;           // 0,8,16,24
    const int cg  = tid >> 6;                // 0..3 -> co sub-group of 4

    unsigned long long acc[4][4];            // [lco][pixel-pair]
    #pragma unroll
    for (int a = 0; a < 4; ++a)
        #pragma unroll
        for (int q = 0; q < 4; ++q) acc[a][q] = 0ull;

    const float* xb  = x + (size_t)b * CIN * HH * WW;
    const float* awb = g_aw + (size_t)b * AWN;

    for (int ch = 0; ch < CIN / CICH; ++ch) {
        __syncthreads();
        // Stage x chunk: 8 ci x 18 x 34 with SAME-padding zero fill
        for (int e = tid; e < CICH * 18 * 34; e += 256) {
            const int lci = e / (18 * 34);
            const int r   = (e / 34) % 18;
            const int c   = e % 34;
            const int gy  = ty + r - 1;
            const int gx  = tx + c - 1;
            float v = 0.0f;
            if (gy >= 0 && gy < HH && gx >= 0 && gx < WW)
                v = xb[((size_t)(ch * CICH + lci)) * HH * WW + gy * WW + gx];
            sx[lci][r][c] = v;
        }
        // Stage weights duplicated: 16 co x 8 ci x 9 taps as (w,w)
        for (int e = tid; e < COG * CICH * 9; e += 256) {
            const int lco = e / (CICH * 9);
            const int rem = e % (CICH * 9);
            const int lci = rem / 9;
            const int t9  = rem % 9;
            const float w =
                awb[((size_t)(cog * COG + lco) * CIN + ch * CICH + lci) * 9 + t9];
            sw2[lco][lci][t9] = make_float2(w, w);
        }
        __syncthreads();

        #pragma unroll 1
        for (int lci = 0; lci < CICH; ++lci) {
            #pragma unroll
            for (int kh = 0; kh < 3; ++kh) {
                // 10 scalar x values -> 9 sliding pairs
                float xr[10];
                #pragma unroll
                for (int i = 0; i < 10; ++i) xr[i] = sx[lci][row + kh][qx + i];
                unsigned long long xp[9];
                #pragma unroll
                for (int j = 0; j < 9; ++j) xp[j] = pk2(xr[j], xr[j + 1]);

                #pragma unroll
                for (int lco = 0; lco < 4; ++lco) {
                    const unsigned long long* wp =
                        reinterpret_cast<const unsigned long long*>(
                            &sw2[cg * 4 + lco][lci][kh * 3]);
                    #pragma unroll
                    for (int k = 0; k < 3; ++k) {
                        const unsigned long long w = wp[k];
                        #pragma unroll
                        for (int q = 0; q < 4; ++q)
                            ffma2(acc[lco][q], xp[2 * q + k], w);
                    }
                }
            }
        }
    }

    // Epilogue: + per-(b,co) bias, relu, 2x float4 store per co
    #pragma unroll
    for (int lco = 0; lco < 4; ++lco) {
        const int co = cog * COG + cg * 4 + lco;
        const float bias = awb[NKW + co];
        float px[8];
        #pragma unroll
        for (int q = 0; q < 4; ++q) {
            float lo, hi;
            upk2(acc[lco][q], lo, hi);
            px[2 * q]     = fmaxf(lo + bias, 0.0f);
            px[2 * q + 1] = fmaxf(hi + bias, 0.0f);
        }
        float* dst = out + (((size_t)b * COUT + co) * HH + (ty + row)) * WW + (tx + qx);
        *reinterpret_cast<float4*>(dst)     = make_float4(px[0], px[1], px[2], px[3]);
        *reinterpret_cast<float4*>(dst + 4) = make_float4(px[4], px[5], px[6], px[7]);
    }
}

// ---------------------------------------------------------------------------
extern "C" void kernel_launch(void* const* d_in, const int* in_sizes, int n_in,
                              void* d_out, int out_size) {
    const float* x  = (const float*)d_in[0];
    const float* z  = (const float*)d_in[1];
    const float* W0 = (const float*)d_in[2];
    const float* b0 = (const float*)d_in[3];
    const float* W1 = (const float*)d_in[4];
    const float* b1 = (const float*)d_in[5];
    const float* W2 = (const float*)d_in[6];
    const float* b2 = (const float*)d_in[7];
    float* out = (float*)d_out;

    mlp_h_kernel<<<BB, 32>>>(z, W0, b0, W1, b1);
    mlp_aw_kernel<<<(AWN + 255) / 256, 256>>>(W2, b2);

    dim3 grid(32, 4, BB);
    conv_kernel<<<grid, 256>>>(x, out);
}

// round 4
// speedup vs baseline: 1.7817x; 1.7817x over previous
#include <cuda_runtime.h>
#include <cuda_fp16.h>
#include <cstdint>

// Problem constants
#define BB   16
#define CIN  64
#define COUT 64
#define HH   128
#define WW   128
#define NKW  36864
#define AWN  36928

// ---------------------------------------------------------------------------
// Device scratch (allocation-free rule)
// ---------------------------------------------------------------------------
__device__ float  g_aw[BB * AWN];
__device__ __half g_xh[BB * HH * WW * CIN];   // NHWC hi split
__device__ __half g_xl[BB * HH * WW * CIN];   // NHWC lo split
__device__ __half g_wh[BB * 9 * COUT * CIN];  // [b][tap][co][ci] hi
__device__ __half g_wl[BB * 9 * COUT * CIN];  // lo

// ---------------------------------------------------------------------------
// Warp MMA helpers (family-agnostic: ldmatrix + mma.sync, sm_80+)
// ---------------------------------------------------------------------------
__device__ __forceinline__ uint32_t smem_u32(const void* p) {
    uint32_t a;
    asm("{ .reg .u64 t; cvta.to.shared.u64 t, %1; cvt.u32.u64 %0, t; }" : "=r"(a) : "l"(p));
    return a;
}
__device__ __forceinline__ void ldsm4(uint32_t (&r)[4], uint32_t addr) {
    asm volatile("ldmatrix.sync.aligned.m8n8.x4.shared.b16 {%0,%1,%2,%3}, [%4];"
                 : "=r"(r[0]), "=r"(r[1]), "=r"(r[2]), "=r"(r[3]) : "r"(addr));
}
__device__ __forceinline__ void mma16816(float (&d)[4], const uint32_t (&a)[4],
                                         uint32_t b0, uint32_t b1) {
    asm volatile(
        "mma.sync.aligned.m16n8k16.row.col.f32.f16.f16.f32 "
        "{%0,%1,%2,%3}, {%4,%5,%6,%7}, {%8,%9}, {%0,%1,%2,%3};"
        : "+f"(d[0]), "+f"(d[1]), "+f"(d[2]), "+f"(d[3])
        : "r"(a[0]), "r"(a[1]), "r"(a[2]), "r"(a[3]), "r"(b0), "r"(b1));
}

// ---------------------------------------------------------------------------
// Fused MLP: computes h per block (tiny), then aw rows. One kernel.
// ---------------------------------------------------------------------------
__global__ __launch_bounds__(256) void mlp_aw_kernel(const float* __restrict__ z,
                                                     const float* __restrict__ W0,
                                                     const float* __restrict__ b0,
                                                     const float* __restrict__ W1,
                                                     const float* __restrict__ b1,
                                                     const float* __restrict__ W2,
                                                     const float* __restrict__ b2) {
    __shared__ float sz[BB * 16];
    __shared__ float h0[BB * 20];
    __shared__ float sh[BB * 30];
    const int tid = threadIdx.x;

    sz[tid] = z[tid];                       // 256 == 16*16
    __syncthreads();
    for (int e = tid; e < BB * 20; e += 256) {
        const int b = e / 20, u = e % 20;
        float s = b0[u];
        #pragma unroll
        for (int j = 0; j < 16; ++j) s += sz[b * 16 + j] * W0[u * 16 + j];
        h0[e] = fmaxf(s, 0.0f);
    }
    __syncthreads();
    for (int e = tid; e < BB * 30; e += 256) {
        const int b = e / 30, u = e % 30;
        float s = b1[u];
        #pragma unroll
        for (int j = 0; j < 20; ++j) s += h0[b * 20 + j] * W1[u * 20 + j];
        sh[e] = fmaxf(s, 0.0f);
    }
    __syncthreads();

    const int i = blockIdx.x * 256 + tid;
    if (i >= AWN) return;
    float w[30];
    #pragma unroll
    for (int j = 0; j < 30; ++j) w[j] = W2[i * 30 + j];
    const float bias = b2[i];
    #pragma unroll
    for (int b = 0; b < BB; ++b) {
        float s = bias;
        #pragma unroll
        for (int j = 0; j < 30; ++j) s += sh[b * 30 + j] * w[j];
        g_aw[b * AWN + i] = fmaxf(s, 0.0f);
    }
}

// ---------------------------------------------------------------------------
// Pack w: g_aw -> [b][tap][co][ci] fp16 hi/lo
// ---------------------------------------------------------------------------
__global__ __launch_bounds__(256) void pack_w_kernel() {
    const int b = blockIdx.x;
    const float* awb = g_aw + (size_t)b * AWN;
    for (int e = threadIdx.x; e < 36864; e += 256) {
        const int ci = e & 63, co = (e >> 6) & 63, s = e >> 12;
        const float v = awb[(co * 64 + ci) * 9 + s];
        const __half hi = __float2half_rn(v);
        const float lo = v - __half2float(hi);
        const size_t o = ((size_t)(b * 9 + s) * 64 + co) * 64 + ci;
        g_wh[o] = hi;
        g_wl[o] = __float2half_rn(lo);
    }
}

// ---------------------------------------------------------------------------
// Pack x: NCHW f32 -> NHWC fp16 hi/lo (smem transpose, coalesced both sides)
// ---------------------------------------------------------------------------
__global__ __launch_bounds__(256) void pack_x_kernel(const float* __restrict__ x) {
    __shared__ float s[64][129];
    const int b = blockIdx.y;
    const int y = blockIdx.x;
    const int tid = threadIdx.x;
    const int px = tid & 127, hh = tid >> 7;
    #pragma unroll
    for (int it = 0; it < 32; ++it) {
        const int ci = it * 2 + hh;
        s[ci][px] = x[((size_t)(b * 64 + ci) * HH + y) * WW + px];
    }
    __syncthreads();
    const int ci2 = tid & 63, pg = tid >> 6;
    #pragma unroll
    for (int it = 0; it < 32; ++it) {
        const int p2 = it * 4 + pg;
        const float v = s[ci2][p2];
        const __half hi = __float2half_rn(v);
        const float lo = v - __half2float(hi);
        const size_t o = ((size_t)(b * HH + y) * WW + p2) * 64 + ci2;
        g_xh[o] = hi;
        g_xl[o] = __float2half_rn(lo);
    }
}

// ---------------------------------------------------------------------------
// Conv: per CTA (b, 2 output rows). D[256 px, 64 co] via mma.sync m16n8k16.
// K = 9 taps x 64 ci x 3 passes (hh, hl, lh). kw shift folded into per-lane
// ldmatrix row addresses (A tiles have 130 rows: px' = -1..128 zero-padded).
// SMEM: weights 9 taps x {hi,lo} 8KB = 147456 | x 4 tiles x 16640 = 66560
// ---------------------------------------------------------------------------
#define W_SMEM  147456
#define X_TILE  16640              // 130 rows * 128B
#define SM_TOTAL (W_SMEM + 4 * X_TILE)   // 214016

__global__ __launch_bounds__(256, 1) void conv_mma_kernel(float* __restrict__ out) {
    extern __shared__ char smem[];
    char* wptr = smem;
    char* xptr = smem + W_SMEM;
    const uint32_t wbase = smem_u32(wptr);
    const uint32_t xbase = smem_u32(xptr);

    const int tid  = threadIdx.x;
    const int wid  = tid >> 5;
    const int lane = tid & 31;
    const int ty = blockIdx.x * 2;
    const int b  = blockIdx.y;

    // ---- load all weights (9 taps, hi+lo), swizzled [row=co][128B] ----
    for (int e = tid; e < 9216; e += 256) {
        const int chunk = e & 7;
        const int co    = (e >> 3) & 63;
        const int split = (e >> 9) & 1;
        const int tap   = e >> 10;
        const __half* src = (split ? g_wl : g_wh) +
            (((size_t)(b * 9 + tap) * 64 + co) * 64 + chunk * 8);
        const uint32_t off = co * 128 + ((chunk * 16) ^ ((co & 7) * 16));
        *reinterpret_cast<uint4*>(wptr + (tap * 2 + split) * 8192 + off) =
            *reinterpret_cast<const uint4*>(src);
    }

    // ---- per-warp geometry ----
    const int orow = wid >> 2;              // 0 or 1
    const int mq   = wid & 3;               // px quarter (32 px)
    const int lrow = lane & 15;             // ldmatrix row within 16
    const int lcol = (lane >> 4) * 16;      // 16B column half
    const uint32_t bxor = ((lane & 7) * 16);

    float acc[2][8][4];
    #pragma unroll
    for (int mt = 0; mt < 2; ++mt)
        #pragma unroll
        for (int nt = 0; nt < 8; ++nt)
            #pragma unroll
            for (int q = 0; q < 4; ++q) acc[mt][nt][q] = 0.0f;

    #pragma unroll 1
    for (int kh = 0; kh < 3; ++kh) {
        __syncthreads();   // weights done (kh=0) / x buffer reusable (kh>0)
        // ---- stage x: 2 image rows x {hi,lo}, 130-row tiles, zero-padded ----
        #pragma unroll 1
        for (int tile = 0; tile < 4; ++tile) {
            const int rowimg = ty + kh - 1 + (tile & 1);
            const __half* src_base = (tile >> 1) ? g_xl : g_xh;
            for (int e = tid; e < 1040; e += 256) {
                const int r = e >> 3;
                const int c = e & 7;
                const int px = r - 1;
                uint4 v = make_uint4(0u, 0u, 0u, 0u);
                if (rowimg >= 0 && rowimg < HH && px >= 0 && px < WW)
                    v = *reinterpret_cast<const uint4*>(src_base +
                        (((size_t)(b * HH + rowimg) * WW + px) * 64 + c * 8));
                const uint32_t off = r * 128 + ((c * 16) ^ ((r & 7) * 16));
                *reinterpret_cast<uint4*>(xptr + tile * X_TILE + off) = v;
            }
        }
        __syncthreads();

        const uint32_t xt_h = xbase + orow * X_TILE;           // hi tile for my orow
        const uint32_t xt_l = xt_h + 2 * X_TILE;               // lo tile

        #pragma unroll 1
        for (int kw = 0; kw < 3; ++kw) {
            const int tap = kh * 3 + kw;
            const uint32_t wt_h = wbase + (tap * 2) * 8192;
            const uint32_t wt_l = wt_h + 8192;
            const int arow0 = mq * 32 + lrow + kw;             // tile row (px + kw)
            const uint32_t axor = (uint32_t)((arow0 & 7) * 16);

            #pragma unroll
            for (int k = 0; k < 4; ++k) {
                uint32_t ah[2][4], al[2][4];
                #pragma unroll
                for (int mt = 0; mt < 2; ++mt) {
                    const uint32_t ad = (uint32_t)((arow0 + 16 * mt) * 128) +
                                        (((uint32_t)(k * 32 + lcol)) ^ axor);
                    ldsm4(ah[mt], xt_h + ad);
                    ldsm4(al[mt], xt_l + ad);
                }
                uint32_t bh[4][4], bl[4][4];
                #pragma unroll
                for (int pr = 0; pr < 4; ++pr) {
                    const uint32_t bd = (uint32_t)((pr * 16 + lrow) * 128) +
                                        (((uint32_t)(k * 32 + lcol)) ^ bxor);
                    ldsm4(bh[pr], wt_h + bd);
                    ldsm4(bl[pr], wt_l + bd);
                }
                // ldsm x4 over 16 co rows: regs {0,2} = n-tile lo8, {1,3} = n-tile hi8
                #pragma unroll
                for (int mt = 0; mt < 2; ++mt)
                    #pragma unroll
                    for (int pr = 0; pr < 4; ++pr) {
                        mma16816(acc[mt][2 * pr + 0], ah[mt], bh[pr][0], bh[pr][2]);
                        mma16816(acc[mt][2 * pr + 1], ah[mt], bh[pr][1], bh[pr][3]);
                        mma16816(acc[mt][2 * pr + 0], ah[mt], bl[pr][0], bl[pr][2]);
                        mma16816(acc[mt][2 * pr + 1], ah[mt], bl[pr][1], bl[pr][3]);
                        mma16816(acc[mt][2 * pr + 0], al[mt], bh[pr][0], bh[pr][2]);
                        mma16816(acc[mt][2 * pr + 1], al[mt], bh[pr][1], bh[pr][3]);
                    }
            }
        }
    }

    // ---- epilogue: fragments -> smem [m][co] (stride 65), then coalesced out ----
    __syncthreads();
    float* Dbuf = reinterpret_cast<float*>(smem);
    #pragma unroll
    for (int mt = 0; mt < 2; ++mt)
        #pragma unroll
        for (int nt = 0; nt < 8; ++nt) {
            const int m0 = orow * 128 + mq * 32 + mt * 16 + (lane >> 2);
            const int co = nt * 8 + (lane & 3) * 2;
            Dbuf[(m0 + 0) * 65 + co]     = acc[mt][nt][0];
            Dbuf[(m0 + 0) * 65 + co + 1] = acc[mt][nt][1];
            Dbuf[(m0 + 8) * 65 + co]     = acc[mt][nt][2];
            Dbuf[(m0 + 8) * 65 + co + 1] = acc[mt][nt][3];
        }
    __syncthreads();

    for (int e = tid; e < 4096; e += 256) {
        const int o2 = e >> 11;
        const int co = (e >> 5) & 63;
        const int px = (e & 31) * 4;
        const int m  = o2 * 128 + px;
        const float bias = g_aw[(size_t)b * AWN + NKW + co];
        float4 v;
        v.x = fmaxf(Dbuf[(m + 0) * 65 + co] + bias, 0.0f);
        v.y = fmaxf(Dbuf[(m + 1) * 65 + co] + bias, 0.0f);
        v.z = fmaxf(Dbuf[(m + 2) * 65 + co] + bias, 0.0f);
        v.w = fmaxf(Dbuf[(m + 3) * 65 + co] + bias, 0.0f);
        *reinterpret_cast<float4*>(out +
            (((size_t)b * COUT + co) * HH + (ty + o2)) * WW + px) = v;
    }
}

// ---------------------------------------------------------------------------
extern "C" void kernel_launch(void* const* d_in, const int* in_sizes, int n_in,
                              void* d_out, int out_size) {
    const float* x  = (const float*)d_in[0];
    const float* z  = (const float*)d_in[1];
    const float* W0 = (const float*)d_in[2];
    const float* b0 = (const float*)d_in[3];
    const float* W1 = (const float*)d_in[4];
    const float* b1 = (const float*)d_in[5];
    const float* W2 = (const float*)d_in[6];
    const float* b2 = (const float*)d_in[7];
    float* out = (float*)d_out;

    cudaFuncSetAttribute(conv_mma_kernel,
                         cudaFuncAttributeMaxDynamicSharedMemorySize, SM_TOTAL);

    mlp_aw_kernel<<<(AWN + 255) / 256, 256>>>(z, W0, b0, W1, b1, W2, b2);
    pack_w_kernel<<<BB, 256>>>();
    {
        dim3 g(HH, BB);
        pack_x_kernel<<<g, 256>>>(x);
    }
    {
        dim3 g(HH / 2, BB);
        conv_mma_kernel<<<g, 256, SM_TOTAL>>>(out);
    }
}

// round 6
// speedup vs baseline: 2.9263x; 1.6424x over previous
#include <cuda_runtime.h>
#include <cuda_fp16.h>
#include <cstdint>

// Problem constants
#define BB   16
#define CIN  64
#define COUT 64
#define HH   128
#define WW   128
#define NKW  36864
#define AWN  36928

// ---------------------------------------------------------------------------
// Device scratch (allocation-free rule)
// ---------------------------------------------------------------------------
__device__ float  g_aw[BB * AWN];
__device__ __half g_xh[BB * HH * WW * CIN];   // NHWC hi split
__device__ __half g_wh[BB * 9 * COUT * CIN];  // [b][tap][co][ci] hi
__device__ __half g_wl[BB * 9 * COUT * CIN];  // lo

// ---------------------------------------------------------------------------
// Warp MMA helpers (family-agnostic: ldmatrix + mma.sync, sm_80+)
// ---------------------------------------------------------------------------
__device__ __forceinline__ uint32_t smem_u32(const void* p) {
    uint32_t a;
    asm("{ .reg .u64 t; cvta.to.shared.u64 t, %1; cvt.u32.u64 %0, t; }" : "=r"(a) : "l"(p));
    return a;
}
__device__ __forceinline__ void ldsm4(uint32_t (&r)[4], uint32_t addr) {
    asm volatile("ldmatrix.sync.aligned.m8n8.x4.shared.b16 {%0,%1,%2,%3}, [%4];"
                 : "=r"(r[0]), "=r"(r[1]), "=r"(r[2]), "=r"(r[3]) : "r"(addr));
}
__device__ __forceinline__ void mma16816(float (&d)[4], const uint32_t (&a)[4],
                                         uint32_t b0, uint32_t b1) {
    asm volatile(
        "mma.sync.aligned.m16n8k16.row.col.f32.f16.f16.f32 "
        "{%0,%1,%2,%3}, {%4,%5,%6,%7}, {%8,%9}, {%0,%1,%2,%3};"
        : "+f"(d[0]), "+f"(d[1]), "+f"(d[2]), "+f"(d[3])
        : "r"(a[0]), "r"(a[1]), "r"(a[2]), "r"(a[3]), "r"(b0), "r"(b1));
}

// ---------------------------------------------------------------------------
// Fused MLP: h per block (tiny), then aw rows. One kernel.
// ---------------------------------------------------------------------------
__global__ __launch_bounds__(256) void mlp_aw_kernel(const float* __restrict__ z,
                                                     const float* __restrict__ W0,
                                                     const float* __restrict__ b0,
                                                     const float* __restrict__ W1,
                                                     const float* __restrict__ b1,
                                                     const float* __restrict__ W2,
                                                     const float* __restrict__ b2) {
    __shared__ float sz[BB * 16];
    __shared__ float h0[BB * 20];
    __shared__ float sh[BB * 30];
    const int tid = threadIdx.x;

    sz[tid] = z[tid];
    __syncthreads();
    for (int e = tid; e < BB * 20; e += 256) {
        const int b = e / 20, u = e % 20;
        float s = b0[u];
        #pragma unroll
        for (int j = 0; j < 16; ++j) s += sz[b * 16 + j] * W0[u * 16 + j];
        h0[e] = fmaxf(s, 0.0f);
    }
    __syncthreads();
    for (int e = tid; e < BB * 30; e += 256) {
        const int b = e / 30, u = e % 30;
        float s = b1[u];
        #pragma unroll
        for (int j = 0; j < 20; ++j) s += h0[b * 20 + j] * W1[u * 20 + j];
        sh[e] = fmaxf(s, 0.0f);
    }
    __syncthreads();

    const int i = blockIdx.x * 256 + tid;
    if (i >= AWN) return;
    float w[30];
    #pragma unroll
    for (int j = 0; j < 30; ++j) w[j] = W2[i * 30 + j];
    const float bias = b2[i];
    #pragma unroll
    for (int b = 0; b < BB; ++b) {
        float s = bias;
        #pragma unroll
        for (int j = 0; j < 30; ++j) s += sh[b * 30 + j] * w[j];
        g_aw[b * AWN + i] = fmaxf(s, 0.0f);
    }
}

// ---------------------------------------------------------------------------
// Pack w: g_aw -> [b][tap][co][ci] fp16 hi/lo
// ---------------------------------------------------------------------------
__global__ __launch_bounds__(256) void pack_w_kernel() {
    const int b = blockIdx.x;
    const float* awb = g_aw + (size_t)b * AWN;
    for (int e = threadIdx.x; e < 36864; e += 256) {
        const int ci = e & 63, co = (e >> 6) & 63, s = e >> 12;
        const float v = awb[(co * 64 + ci) * 9 + s];
        const __half hi = __float2half_rn(v);
        const float lo = v - __half2float(hi);
        const size_t o = ((size_t)(b * 9 + s) * 64 + co) * 64 + ci;
        g_wh[o] = hi;
        g_wl[o] = __float2half_rn(lo);
    }
}

// ---------------------------------------------------------------------------
// Pack x: NCHW f32 -> NHWC fp16 hi (smem transpose, coalesced both sides)
// ---------------------------------------------------------------------------
__global__ __launch_bounds__(256) void pack_x_kernel(const float* __restrict__ x) {
    __shared__ float s[64][129];
    const int b = blockIdx.y;
    const int y = blockIdx.x;
    const int tid = threadIdx.x;
    const int px = tid & 127, hh = tid >> 7;
    #pragma unroll
    for (int it = 0; it < 32; ++it) {
        const int ci = it * 2 + hh;
        s[ci][px] = x[((size_t)(b * 64 + ci) * HH + y) * WW + px];
    }
    __syncthreads();
    const int ci2 = tid & 63, pg = tid >> 6;
    #pragma unroll
    for (int it = 0; it < 32; ++it) {
        const int p2 = it * 4 + pg;
        g_xh[((size_t)(b * HH + y) * WW + p2) * 64 + ci2] =
            __float2half_rn(s[ci2][p2]);
    }
}

// ---------------------------------------------------------------------------
// Conv: per CTA (b, 2 output rows). D[256 px, 64 co] via mma.sync m16n8k16.
// K = 9 taps x 64 ci x 2 passes (x_hi*w_hi + x_hi*w_lo). kw folded into
// per-lane ldmatrix row addresses (x tiles have 130 rows, zero-padded).
// 512 threads / 16 warps: warp = (orow, px-quarter, co-half) -> 32px x 32co.
// SMEM: weights 9 taps x {hi,lo} 8KB = 147456 | x 2 tiles x 16640 = 33280
// ---------------------------------------------------------------------------
#define W_SMEM  147456
#define X_TILE  16640                       // 130 rows * 128B
#define SM_TOTAL (W_SMEM + 2 * X_TILE)      // 180736

__global__ __launch_bounds__(512, 1) void conv_mma_kernel(float* __restrict__ out) {
    extern __shared__ char smem[];
    char* wptr = smem;
    char* xptr = smem + W_SMEM;
    const uint32_t wbase = smem_u32(wptr);
    const uint32_t xbase = smem_u32(xptr);

    const int tid  = threadIdx.x;
    const int wid  = tid >> 5;
    const int lane = tid & 31;
    const int ty = blockIdx.x * 2;
    const int b  = blockIdx.y;

    // ---- load all weights (9 taps, hi+lo), swizzled [row=co][128B] ----
    for (int e = tid; e < 9216; e += 512) {
        const int chunk = e & 7;
        const int co    = (e >> 3) & 63;
        const int split = (e >> 9) & 1;
        const int tap   = e >> 10;
        const __half* src = (split ? g_wl : g_wh) +
            (((size_t)(b * 9 + tap) * 64 + co) * 64 + chunk * 8);
        const uint32_t off = co * 128 + ((chunk * 16) ^ ((co & 7) * 16));
        *reinterpret_cast<uint4*>(wptr + (tap * 2 + split) * 8192 + off) =
            *reinterpret_cast<const uint4*>(src);
    }

    // ---- per-warp geometry: 16 warps = orow(2) x mq(4) x ch(2) ----
    const int orow = wid >> 3;              // 0 or 1
    const int mq   = (wid >> 1) & 3;        // px quarter (32 px)
    const int ch   = wid & 1;               // co half (32 co)
    const int lrow = lane & 15;
    const int lcol = (lane >> 4) * 16;
    const uint32_t bxor = (uint32_t)((lane & 7) * 16);

    float acc[2][2][2][4];                  // [mt][pr][half][4]
    #pragma unroll
    for (int mt = 0; mt < 2; ++mt)
        #pragma unroll
        for (int pr = 0; pr < 2; ++pr)
            #pragma unroll
            for (int h = 0; h < 2; ++h)
                #pragma unroll
                for (int q = 0; q < 4; ++q) acc[mt][pr][h][q] = 0.0f;

    #pragma unroll 1
    for (int kh = 0; kh < 3; ++kh) {
        __syncthreads();   // weights done (kh=0) / x buffer reusable (kh>0)
        // ---- stage x: 2 image rows (hi split), 130-row tiles, zero-padded ----
        #pragma unroll
        for (int tile = 0; tile < 2; ++tile) {
            const int rowimg = ty + kh - 1 + tile;
            for (int e = tid; e < 1040; e += 512) {
                const int r = e >> 3;
                const int c = e & 7;
                const int px = r - 1;
                uint4 v = make_uint4(0u, 0u, 0u, 0u);
                if (rowimg >= 0 && rowimg < HH && px >= 0 && px < WW)
                    v = *reinterpret_cast<const uint4*>(g_xh +
                        (((size_t)(b * HH + rowimg) * WW + px) * 64 + c * 8));
                const uint32_t off = r * 128 + ((c * 16) ^ ((r & 7) * 16));
                *reinterpret_cast<uint4*>(xptr + tile * X_TILE + off) = v;
            }
        }
        __syncthreads();

        const uint32_t xt = xbase + orow * X_TILE;

        #pragma unroll 1
        for (int kw = 0; kw < 3; ++kw) {
            const int tap = kh * 3 + kw;
            const uint32_t wt_h = wbase + (tap * 2) * 8192;
            const uint32_t wt_l = wt_h + 8192;
            const int arow0 = mq * 32 + lrow + kw;
            const uint32_t axor = (uint32_t)((arow0 & 7) * 16);

            #pragma unroll
            for (int k = 0; k < 4; ++k) {
                uint32_t ah[2][4];
                #pragma unroll
                for (int mt = 0; mt < 2; ++mt) {
                    const uint32_t ad = (uint32_t)((arow0 + 16 * mt) * 128) +
                                        (((uint32_t)(k * 32 + lcol)) ^ axor);
                    ldsm4(ah[mt], xt + ad);
                }
                uint32_t bh[2][4], bl[2][4];
                #pragma unroll
                for (int pr = 0; pr < 2; ++pr) {
                    const uint32_t bd = (uint32_t)(((ch * 2 + pr) * 16 + lrow) * 128) +
                                        (((uint32_t)(k * 32 + lcol)) ^ bxor);
                    ldsm4(bh[pr], wt_h + bd);
                    ldsm4(bl[pr], wt_l + bd);
                }
                #pragma unroll
                for (int mt = 0; mt < 2; ++mt)
                    #pragma unroll
                    for (int pr = 0; pr < 2; ++pr) {
                        mma16816(acc[mt][pr][0], ah[mt], bh[pr][0], bh[pr][2]);
                        mma16816(acc[mt][pr][1], ah[mt], bh[pr][1], bh[pr][3]);
                        mma16816(acc[mt][pr][0], ah[mt], bl[pr][0], bl[pr][2]);
                        mma16816(acc[mt][pr][1], ah[mt], bl[pr][1], bl[pr][3]);
                    }
            }
        }
    }

    // ---- epilogue: fragments -> smem [m][co] (stride 65), then coalesced out ----
    __syncthreads();
    float* Dbuf = reinterpret_cast<float*>(smem);
    #pragma unroll
    for (int mt = 0; mt < 2; ++mt)
        #pragma unroll
        for (int pr = 0; pr < 2; ++pr)
            #pragma unroll
            for (int h = 0; h < 2; ++h) {
                const int m0 = orow * 128 + mq * 32 + mt * 16 + (lane >> 2);
                const int co = ch * 32 + pr * 16 + h * 8 + (lane & 3) * 2;
                Dbuf[(m0 + 0) * 65 + co]     = acc[mt][pr][h][0];
                Dbuf[(m0 + 0) * 65 + co + 1] = acc[mt][pr][h][1];
                Dbuf[(m0 + 8) * 65 + co]     = acc[mt][pr][h][2];
                Dbuf[(m0 + 8) * 65 + co + 1] = acc[mt][pr][h][3];
            }
    __syncthreads();

    for (int e = tid; e < 4096; e += 512) {
        const int o2 = e >> 11;
        const int co = (e >> 5) & 63;
        const int px = (e & 31) * 4;
        const int m  = o2 * 128 + px;
        const float bias = g_aw[(size_t)b * AWN + NKW + co];
        float4 v;
        v.x = fmaxf(Dbuf[(m + 0) * 65 + co] + bias, 0.0f);
        v.y = fmaxf(Dbuf[(m + 1) * 65 + co] + bias, 0.0f);
        v.z = fmaxf(Dbuf[(m + 2) * 65 + co] + bias, 0.0f);
        v.w = fmaxf(Dbuf[(m + 3) * 65 + co] + bias, 0.0f);
        *reinterpret_cast<float4*>(out +
            (((size_t)b * COUT + co) * HH + (ty + o2)) * WW + px) = v;
    }
}

// ---------------------------------------------------------------------------
extern "C" void kernel_launch(void* const* d_in, const int* in_sizes, int n_in,
                              void* d_out, int out_size) {
    const float* x  = (const float*)d_in[0];
    const float* z  = (const float*)d_in[1];
    const float* W0 = (const float*)d_in[2];
    const float* b0 = (const float*)d_in[3];
    const float* W1 = (const float*)d_in[4];
    const float* b1 = (const float*)d_in[5];
    const float* W2 = (const float*)d_in[6];
    const float* b2 = (const float*)d_in[7];
    float* out = (float*)d_out;

    cudaFuncSetAttribute(conv_mma_kernel,
                         cudaFuncAttributeMaxDynamicSharedMemorySize, SM_TOTAL);

    mlp_aw_kernel<<<(AWN + 255) / 256, 256>>>(z, W0, b0, W1, b1, W2, b2);
    pack_w_kernel<<<BB, 256>>>();
    {
        dim3 g(HH, BB);
        pack_x_kernel<<<g, 256>>>(x);
    }
    {
        dim3 g(HH / 2, BB);
        conv_mma_kernel<<<g, 512, SM_TOTAL>>>(out);
    }
}

// round 7
// speedup vs baseline: 3.1902x; 1.0902x over previous
#include <cuda_runtime.h>
#include <cuda_fp16.h>
#include <cstdint>

// Problem constants
#define BB   16
#define CIN  64
#define COUT 64
#define HH   128
#define WW   128
#define NKW  36864
#define AWN  36928

// ---------------------------------------------------------------------------
// Device scratch (allocation-free rule)
// ---------------------------------------------------------------------------
__device__ float  g_aw[BB * AWN];
__device__ __half g_xh[BB * HH * WW * CIN];   // NHWC hi split
__device__ __half g_wh[BB * 9 * COUT * CIN];  // [b][tap][co][ci] hi
__device__ __half g_wl[BB * 9 * COUT * CIN];  // lo

// ---------------------------------------------------------------------------
// Warp MMA helpers (family-agnostic: ldmatrix + mma.sync, sm_80+)
// ---------------------------------------------------------------------------
__device__ __forceinline__ uint32_t smem_u32(const void* p) {
    uint32_t a;
    asm("{ .reg .u64 t; cvta.to.shared.u64 t, %1; cvt.u32.u64 %0, t; }" : "=r"(a) : "l"(p));
    return a;
}
__device__ __forceinline__ void ldsm4(uint32_t (&r)[4], uint32_t addr) {
    asm volatile("ldmatrix.sync.aligned.m8n8.x4.shared.b16 {%0,%1,%2,%3}, [%4];"
                 : "=r"(r[0]), "=r"(r[1]), "=r"(r[2]), "=r"(r[3]) : "r"(addr));
}
__device__ __forceinline__ void mma16816(float (&d)[4], const uint32_t (&a)[4],
                                         uint32_t b0, uint32_t b1) {
    asm volatile(
        "mma.sync.aligned.m16n8k16.row.col.f32.f16.f16.f32 "
        "{%0,%1,%2,%3}, {%4,%5,%6,%7}, {%8,%9}, {%0,%1,%2,%3};"
        : "+f"(d[0]), "+f"(d[1]), "+f"(d[2]), "+f"(d[3])
        : "r"(a[0]), "r"(a[1]), "r"(a[2]), "r"(a[3]), "r"(b0), "r"(b1));
}

// ---------------------------------------------------------------------------
// Fused MLP: h per block (tiny), then aw rows. One kernel.
// ---------------------------------------------------------------------------
__global__ __launch_bounds__(256) void mlp_aw_kernel(const float* __restrict__ z,
                                                     const float* __restrict__ W0,
                                                     const float* __restrict__ b0,
                                                     const float* __restrict__ W1,
                                                     const float* __restrict__ b1,
                                                     const float* __restrict__ W2,
                                                     const float* __restrict__ b2) {
    __shared__ float sz[BB * 16];
    __shared__ float h0[BB * 20];
    __shared__ float sh[BB * 30];
    const int tid = threadIdx.x;

    sz[tid] = z[tid];
    __syncthreads();
    for (int e = tid; e < BB * 20; e += 256) {
        const int b = e / 20, u = e % 20;
        float s = b0[u];
        #pragma unroll
        for (int j = 0; j < 16; ++j) s += sz[b * 16 + j] * W0[u * 16 + j];
        h0[e] = fmaxf(s, 0.0f);
    }
    __syncthreads();
    for (int e = tid; e < BB * 30; e += 256) {
        const int b = e / 30, u = e % 30;
        float s = b1[u];
        #pragma unroll
        for (int j = 0; j < 20; ++j) s += h0[b * 20 + j] * W1[u * 20 + j];
        sh[e] = fmaxf(s, 0.0f);
    }
    __syncthreads();

    const int i = blockIdx.x * 256 + tid;
    if (i >= AWN) return;
    float w[30];
    #pragma unroll
    for (int j = 0; j < 30; ++j) w[j] = W2[i * 30 + j];
    const float bias = b2[i];
    #pragma unroll
    for (int b = 0; b < BB; ++b) {
        float s = bias;
        #pragma unroll
        for (int j = 0; j < 30; ++j) s += sh[b * 30 + j] * w[j];
        g_aw[b * AWN + i] = fmaxf(s, 0.0f);
    }
}

// ---------------------------------------------------------------------------
// Pack w: g_aw -> [b][tap][co][ci] fp16 hi/lo
// ---------------------------------------------------------------------------
__global__ __launch_bounds__(256) void pack_w_kernel() {
    const int b = blockIdx.x;
    const float* awb = g_aw + (size_t)b * AWN;
    for (int e = threadIdx.x; e < 36864; e += 256) {
        const int ci = e & 63, co = (e >> 6) & 63, s = e >> 12;
        const float v = awb[(co * 64 + ci) * 9 + s];
        const __half hi = __float2half_rn(v);
        const float lo = v - __half2float(hi);
        const size_t o = ((size_t)(b * 9 + s) * 64 + co) * 64 + ci;
        g_wh[o] = hi;
        g_wl[o] = __float2half_rn(lo);
    }
}

// ---------------------------------------------------------------------------
// Pack x: NCHW f32 -> NHWC fp16 hi (smem transpose, coalesced both sides)
// ---------------------------------------------------------------------------
__global__ __launch_bounds__(256) void pack_x_kernel(const float* __restrict__ x) {
    __shared__ float s[64][129];
    const int b = blockIdx.y;
    const int y = blockIdx.x;
    const int tid = threadIdx.x;
    const int px = tid & 127, hh = tid >> 7;
    #pragma unroll
    for (int it = 0; it < 32; ++it) {
        const int ci = it * 2 + hh;
        s[ci][px] = x[((size_t)(b * 64 + ci) * HH + y) * WW + px];
    }
    __syncthreads();
    const int ci2 = tid & 63, pg = tid >> 6;
    #pragma unroll
    for (int it = 0; it < 32; ++it) {
        const int p2 = it * 4 + pg;
        g_xh[((size_t)(b * HH + y) * WW + p2) * 64 + ci2] =
            __float2half_rn(s[ci2][p2]);
    }
}

// ---------------------------------------------------------------------------
// Conv, persistent-slab version.
// Grid: (9 slabs, 16 batch) = 144 CTAs, 512 threads. Each CTA:
//   - stages ALL weights once (9 taps x {hi,lo} x 64co x 128B = 144KB)
//   - loops over its ~7 ty tiles; per tile stages 4 image rows (66.5KB)
//     covering all 3 kh windows -> mainloop (576 MMA/warp) has NO barriers.
// Epilogue Dbuf aliases the x region (both 66560 B).
// ---------------------------------------------------------------------------
#define W_SMEM  147456
#define X_TILE  16640                       // 130 rows * 128B
#define SM_TOTAL (W_SMEM + 4 * X_TILE)      // 214016

__global__ __launch_bounds__(512, 1) void conv_mma_kernel(float* __restrict__ out) {
    extern __shared__ char smem[];
    char* wptr = smem;
    char* xptr = smem + W_SMEM;
    const uint32_t wbase = smem_u32(wptr);
    const uint32_t xbase = smem_u32(xptr);

    const int tid  = threadIdx.x;
    const int wid  = tid >> 5;
    const int lane = tid & 31;
    const int slab = blockIdx.x;            // 0..8
    const int b    = blockIdx.y;

    const int t0 = (64 * slab) / 9;
    const int t1 = (64 * (slab + 1)) / 9;

    // ---- stage ALL weights once (9 taps, hi+lo), swizzled [row=co][128B] ----
    for (int e = tid; e < 9216; e += 512) {
        const int chunk = e & 7;
        const int co    = (e >> 3) & 63;
        const int split = (e >> 9) & 1;
        const int tap   = e >> 10;
        const __half* src = (split ? g_wl : g_wh) +
            (((size_t)(b * 9 + tap) * 64 + co) * 64 + chunk * 8);
        const uint32_t off = co * 128 + ((chunk * 16) ^ ((co & 7) * 16));
        *reinterpret_cast<uint4*>(wptr + (tap * 2 + split) * 8192 + off) =
            *reinterpret_cast<const uint4*>(src);
    }

    // ---- per-warp geometry: 16 warps = orow(2) x mq(4) x ch(2) ----
    const int orow = wid >> 3;
    const int mq   = (wid >> 1) & 3;
    const int ch   = wid & 1;
    const int lrow = lane & 15;
    const int lcol = (lane >> 4) * 16;
    const uint32_t bxor = (uint32_t)((lane & 7) * 16);

    for (int tile = t0; tile < t1; ++tile) {
        const int ty = tile * 2;
        __syncthreads();   // weights ready (first iter) / prev epilogue done

        // ---- stage 4 image rows (ty-1 .. ty+2), 130-row tiles, zero-padded ----
        #pragma unroll
        for (int j = 0; j < 4; ++j) {
            const int rowimg = ty - 1 + j;
            for (int e = tid; e < 1040; e += 512) {
                const int r = e >> 3;
                const int c = e & 7;
                const int px = r - 1;
                uint4 v = make_uint4(0u, 0u, 0u, 0u);
                if (rowimg >= 0 && rowimg < HH && px >= 0 && px < WW)
                    v = *reinterpret_cast<const uint4*>(g_xh +
                        (((size_t)(b * HH + rowimg) * WW + px) * 64 + c * 8));
                const uint32_t off = r * 128 + ((c * 16) ^ ((r & 7) * 16));
                *reinterpret_cast<uint4*>(xptr + j * X_TILE + off) = v;
            }
        }
        __syncthreads();

        float acc[2][2][2][4];              // [mt][pr][half][4]
        #pragma unroll
        for (int mt = 0; mt < 2; ++mt)
            #pragma unroll
            for (int pr = 0; pr < 2; ++pr)
                #pragma unroll
                for (int h = 0; h < 2; ++h)
                    #pragma unroll
                    for (int q = 0; q < 4; ++q) acc[mt][pr][h][q] = 0.0f;

        // ---- barrier-free mainloop: 9 taps x 4 k-steps ----
        #pragma unroll 1
        for (int kh = 0; kh < 3; ++kh) {
            const uint32_t xt = xbase + (orow + kh) * X_TILE;
            #pragma unroll
            for (int kw = 0; kw < 3; ++kw) {
                const int tap = kh * 3 + kw;
                const uint32_t wt_h = wbase + (tap * 2) * 8192;
                const uint32_t wt_l = wt_h + 8192;
                const int arow0 = mq * 32 + lrow + kw;
                const uint32_t axor = (uint32_t)((arow0 & 7) * 16);

                #pragma unroll
                for (int k = 0; k < 4; ++k) {
                    uint32_t ah[2][4];
                    #pragma unroll
                    for (int mt = 0; mt < 2; ++mt) {
                        const uint32_t ad = (uint32_t)((arow0 + 16 * mt) * 128) +
                                            (((uint32_t)(k * 32 + lcol)) ^ axor);
                        ldsm4(ah[mt], xt + ad);
                    }
                    uint32_t bh[2][4], bl[2][4];
                    #pragma unroll
                    for (int pr = 0; pr < 2; ++pr) {
                        const uint32_t bd = (uint32_t)(((ch * 2 + pr) * 16 + lrow) * 128) +
                                            (((uint32_t)(k * 32 + lcol)) ^ bxor);
                        ldsm4(bh[pr], wt_h + bd);
                        ldsm4(bl[pr], wt_l + bd);
                    }
                    // all hi-split MMAs first, then lo-split: acc reuse distance 8
                    #pragma unroll
                    for (int mt = 0; mt < 2; ++mt)
                        #pragma unroll
                        for (int pr = 0; pr < 2; ++pr) {
                            mma16816(acc[mt][pr][0], ah[mt], bh[pr][0], bh[pr][2]);
                            mma16816(acc[mt][pr][1], ah[mt], bh[pr][1], bh[pr][3]);
                        }
                    #pragma unroll
                    for (int mt = 0; mt < 2; ++mt)
                        #pragma unroll
                        for (int pr = 0; pr < 2; ++pr) {
                            mma16816(acc[mt][pr][0], ah[mt], bl[pr][0], bl[pr][2]);
                            mma16816(acc[mt][pr][1], ah[mt], bl[pr][1], bl[pr][3]);
                        }
                }
            }
        }

        // ---- epilogue: fragments -> Dbuf [m][co] (stride 65), coalesced out ----
        __syncthreads();
        float* Dbuf = reinterpret_cast<float*>(xptr);
        #pragma unroll
        for (int mt = 0; mt < 2; ++mt)
            #pragma unroll
            for (int pr = 0; pr < 2; ++pr)
                #pragma unroll
                for (int h = 0; h < 2; ++h) {
                    const int m0 = orow * 128 + mq * 32 + mt * 16 + (lane >> 2);
                    const int co = ch * 32 + pr * 16 + h * 8 + (lane & 3) * 2;
                    Dbuf[(m0 + 0) * 65 + co]     = acc[mt][pr][h][0];
                    Dbuf[(m0 + 0) * 65 + co + 1] = acc[mt][pr][h][1];
                    Dbuf[(m0 + 8) * 65 + co]     = acc[mt][pr][h][2];
                    Dbuf[(m0 + 8) * 65 + co + 1] = acc[mt][pr][h][3];
                }
        __syncthreads();

        for (int e = tid; e < 4096; e += 512) {
            const int o2 = e >> 11;
            const int co = (e >> 5) & 63;
            const int px = (e & 31) * 4;
            const int m  = o2 * 128 + px;
            const float bias = g_aw[(size_t)b * AWN + NKW + co];
            float4 v;
            v.x = fmaxf(Dbuf[(m + 0) * 65 + co] + bias, 0.0f);
            v.y = fmaxf(Dbuf[(m + 1) * 65 + co] + bias, 0.0f);
            v.z = fmaxf(Dbuf[(m + 2) * 65 + co] + bias, 0.0f);
            v.w = fmaxf(Dbuf[(m + 3) * 65 + co] + bias, 0.0f);
            *reinterpret_cast<float4*>(out +
                (((size_t)b * COUT + co) * HH + (ty + o2)) * WW + px) = v;
        }
    }
}

// ---------------------------------------------------------------------------
extern "C" void kernel_launch(void* const* d_in, const int* in_sizes, int n_in,
                              void* d_out, int out_size) {
    const float* x  = (const float*)d_in[0];
    const float* z  = (const float*)d_in[1];
    const float* W0 = (const float*)d_in[2];
    const float* b0 = (const float*)d_in[3];
    const float* W1 = (const float*)d_in[4];
    const float* b1 = (const float*)d_in[5];
    const float* W2 = (const float*)d_in[6];
    const float* b2 = (const float*)d_in[7];
    float* out = (float*)d_out;

    cudaFuncSetAttribute(conv_mma_kernel,
                         cudaFuncAttributeMaxDynamicSharedMemorySize, SM_TOTAL);

    mlp_aw_kernel<<<(AWN + 255) / 256, 256>>>(z, W0, b0, W1, b1, W2, b2);
    pack_w_kernel<<<BB, 256>>>();
    {
        dim3 g(HH, BB);
        pack_x_kernel<<<g, 256>>>(x);
    }
    {
        dim3 g(9, BB);
        conv_mma_kernel<<<g, 512, SM_TOTAL>>>(out);
    }
}

// round 8
// speedup vs baseline: 3.7252x; 1.1677x over previous
#include <cuda_runtime.h>
#include <cuda_fp16.h>
#include <cstdint>

// Problem constants
#define BB   16
#define CIN  64
#define COUT 64
#define HH   128
#define WW   128
#define NKW  36864
#define AWN  36928

// ---------------------------------------------------------------------------
// Device scratch (allocation-free rule)
// ---------------------------------------------------------------------------
__device__ float  g_bias[BB * COUT];
__device__ __half g_xh[BB * HH * WW * CIN];   // NHWC hi split
__device__ __half g_wh[BB * 9 * COUT * CIN];  // [b][tap][co][ci] hi
__device__ __half g_wl[BB * 9 * COUT * CIN];  // lo

// ---------------------------------------------------------------------------
// Warp MMA helpers (family-agnostic: ldmatrix + mma.sync, sm_80+)
// ---------------------------------------------------------------------------
__device__ __forceinline__ uint32_t smem_u32(const void* p) {
    uint32_t a;
    asm("{ .reg .u64 t; cvta.to.shared.u64 t, %1; cvt.u32.u64 %0, t; }" : "=r"(a) : "l"(p));
    return a;
}
__device__ __forceinline__ void ldsm4(uint32_t (&r)[4], uint32_t addr) {
    asm volatile("ldmatrix.sync.aligned.m8n8.x4.shared.b16 {%0,%1,%2,%3}, [%4];"
                 : "=r"(r[0]), "=r"(r[1]), "=r"(r[2]), "=r"(r[3]) : "r"(addr));
}
__device__ __forceinline__ void mma16816(float (&d)[4], const uint32_t (&a)[4],
                                         uint32_t b0, uint32_t b1) {
    asm volatile(
        "mma.sync.aligned.m16n8k16.row.col.f32.f16.f16.f32 "
        "{%0,%1,%2,%3}, {%4,%5,%6,%7}, {%8,%9}, {%0,%1,%2,%3};"
        : "+f"(d[0]), "+f"(d[1]), "+f"(d[2]), "+f"(d[3])
        : "r"(a[0]), "r"(a[1]), "r"(a[2]), "r"(a[3]), "r"(b0), "r"(b1));
}

// ---------------------------------------------------------------------------
// Fused MLP + weight pack: h -> aw -> {g_wh, g_wl, g_bias} directly.
// ---------------------------------------------------------------------------
__global__ __launch_bounds__(256) void mlp_aw_kernel(const float* __restrict__ z,
                                                     const float* __restrict__ W0,
                                                     const float* __restrict__ b0,
                                                     const float* __restrict__ W1,
                                                     const float* __restrict__ b1,
                                                     const float* __restrict__ W2,
                                                     const float* __restrict__ b2) {
    __shared__ float sz[BB * 16];
    __shared__ float h0[BB * 20];
    __shared__ float sh[BB * 30];
    const int tid = threadIdx.x;

    sz[tid] = z[tid];
    __syncthreads();
    for (int e = tid; e < BB * 20; e += 256) {
        const int b = e / 20, u = e % 20;
        float s = b0[u];
        #pragma unroll
        for (int j = 0; j < 16; ++j) s += sz[b * 16 + j] * W0[u * 16 + j];
        h0[e] = fmaxf(s, 0.0f);
    }
    __syncthreads();
    for (int e = tid; e < BB * 30; e += 256) {
        const int b = e / 30, u = e % 30;
        float s = b1[u];
        #pragma unroll
        for (int j = 0; j < 20; ++j) s += h0[b * 20 + j] * W1[u * 20 + j];
        sh[e] = fmaxf(s, 0.0f);
    }
    __syncthreads();

    const int i = blockIdx.x * 256 + tid;
    if (i >= AWN) return;
    float w[30];
    #pragma unroll
    for (int j = 0; j < 30; ++j) w[j] = W2[i * 30 + j];
    const float bias = b2[i];

    if (i < NKW) {
        const int co  = i / 576;
        const int rem = i % 576;
        const int ci  = rem / 9;
        const int s9  = rem % 9;
        #pragma unroll
        for (int b = 0; b < BB; ++b) {
            float s = bias;
            #pragma unroll
            for (int j = 0; j < 30; ++j) s += sh[b * 30 + j] * w[j];
            const float v = fmaxf(s, 0.0f);
            const __half hi = __float2half_rn(v);
            const float lo = v - __half2float(hi);
            const size_t o = ((size_t)(b * 9 + s9) * 64 + co) * 64 + ci;
            g_wh[o] = hi;
            g_wl[o] = __float2half_rn(lo);
        }
    } else {
        const int co = i - NKW;
        #pragma unroll
        for (int b = 0; b < BB; ++b) {
            float s = bias;
            #pragma unroll
            for (int j = 0; j < 30; ++j) s += sh[b * 30 + j] * w[j];
            g_bias[b * 64 + co] = fmaxf(s, 0.0f);
        }
    }
}

// ---------------------------------------------------------------------------
// Pack x: NCHW f32 -> NHWC fp16 hi (smem transpose, coalesced both sides)
// ---------------------------------------------------------------------------
__global__ __launch_bounds__(256) void pack_x_kernel(const float* __restrict__ x) {
    __shared__ float s[64][129];
    const int b = blockIdx.y;
    const int y = blockIdx.x;
    const int tid = threadIdx.x;
    const int px = tid & 127, hh = tid >> 7;
    #pragma unroll
    for (int it = 0; it < 32; ++it) {
        const int ci = it * 2 + hh;
        s[ci][px] = x[((size_t)(b * 64 + ci) * HH + y) * WW + px];
    }
    __syncthreads();
    const int ci2 = tid & 63, pg = tid >> 6;
    #pragma unroll
    for (int it = 0; it < 32; ++it) {
        const int p2 = it * 4 + pg;
        g_xh[((size_t)(b * HH + y) * WW + p2) * 64 + ci2] =
            __float2half_rn(s[ci2][p2]);
    }
}

// ---------------------------------------------------------------------------
// Conv, persistent-slab, fat-warp version.
// Grid: (8 slabs, 16 batch) = 128 CTAs, 512 threads, 4 tiles/CTA.
// Tile = 4 output rows (512 px) x 64 co. Warp = 64 px x 32 co (mt=4, pr=2):
// per k-step 8 LDSM.x4 / 32 MMA (ratio 0.25, was 0.375).
// x: ring of 4 row-buffers; 3 stage phases/tile (4+1+1 rows = 6 minimal).
// Weights (144KB) resident for the whole CTA. Epilogue: direct float2 stores.
// ---------------------------------------------------------------------------
#define W_SMEM  147456
#define X_TILE  16640                       // 130 rows * 128B
#define SM_TOTAL (W_SMEM + 4 * X_TILE)      // 214016

__global__ __launch_bounds__(512, 1) void conv_mma_kernel(float* __restrict__ out) {
    extern __shared__ char smem[];
    char* wptr = smem;
    char* xptr = smem + W_SMEM;
    const uint32_t wbase = smem_u32(wptr);
    const uint32_t xbase = smem_u32(xptr);

    const int tid  = threadIdx.x;
    const int wid  = tid >> 5;
    const int lane = tid & 31;
    const int slab = blockIdx.x;            // 0..7
    const int b    = blockIdx.y;

    // ---- stage ALL weights once (9 taps, hi+lo), swizzled [row=co][128B] ----
    for (int e = tid; e < 9216; e += 512) {
        const int chunk = e & 7;
        const int co    = (e >> 3) & 63;
        const int split = (e >> 9) & 1;
        const int tap   = e >> 10;
        const __half* src = (split ? g_wl : g_wh) +
            (((size_t)(b * 9 + tap) * 64 + co) * 64 + chunk * 8);
        const uint32_t off = co * 128 + ((chunk * 16) ^ ((co & 7) * 16));
        *reinterpret_cast<uint4*>(wptr + (tap * 2 + split) * 8192 + off) =
            *reinterpret_cast<const uint4*>(src);
    }

    // ---- per-warp geometry: 16 warps = mq(8) x ch(2); warp = 64px x 32co ----
    const int mq   = wid >> 1;              // 0..7 -> 64-px slice
    const int ch   = wid & 1;               // co half (32 co)
    const int rloc = mq >> 1;               // local image row 0..3
    const int xh64 = (mq & 1) * 64;         // 0 or 64 within image row
    const int lrow = lane & 15;
    const int lcol = (lane >> 4) * 16;
    const uint32_t bxor = (uint32_t)((lane & 7) * 16);

    const float* biasp = g_bias + b * 64;

    for (int tile = slab * 4; tile < slab * 4 + 4; ++tile) {
        const int ty = tile * 4;

        float acc[4][2][2][4];              // [mt][pr][half][4]
        #pragma unroll
        for (int mt = 0; mt < 4; ++mt)
            #pragma unroll
            for (int pr = 0; pr < 2; ++pr)
                #pragma unroll
                for (int h = 0; h < 2; ++h)
                    #pragma unroll
                    for (int q = 0; q < 4; ++q) acc[mt][pr][h][q] = 0.0f;

        // 3 phases: kh = phase; phase 0 stages rows ty-1..ty+2 (buffers 0..3),
        // phase p>0 stages row ty+2+p into buffer (3+p)&3.
        #pragma unroll 1
        for (int kh = 0; kh < 3; ++kh) {
            __syncthreads();   // previous phase's MMAs (or weight load) done
            const int j0 = (kh == 0) ? 0 : (3 + kh) & 7;   // 0 -> stage 4; else 1
            if (kh == 0) {
                #pragma unroll 1
                for (int j = 0; j < 4; ++j) {
                    const int rowimg = ty - 1 + j;
                    for (int e = tid; e < 1040; e += 512) {
                        const int r = e >> 3;
                        const int c = e & 7;
                        const int px = r - 1;
                        uint4 v = make_uint4(0u, 0u, 0u, 0u);
                        if (rowimg >= 0 && rowimg < HH && px >= 0 && px < WW)
                            v = *reinterpret_cast<const uint4*>(g_xh +
                                (((size_t)(b * HH + rowimg) * WW + px) * 64 + c * 8));
                        const uint32_t off = r * 128 + ((c * 16) ^ ((r & 7) * 16));
                        *reinterpret_cast<uint4*>(xptr + j * X_TILE + off) = v;
                    }
                }
            } else {
                const int buf = (3 + kh) & 3;
                const int rowimg = ty + 2 + kh;
                for (int e = tid; e < 1040; e += 512) {
                    const int r = e >> 3;
                    const int c = e & 7;
                    const int px = r - 1;
                    uint4 v = make_uint4(0u, 0u, 0u, 0u);
                    if (rowimg < HH && px >= 0 && px < WW)
                        v = *reinterpret_cast<const uint4*>(g_xh +
                            (((size_t)(b * HH + rowimg) * WW + px) * 64 + c * 8));
                    const uint32_t off = r * 128 + ((c * 16) ^ ((r & 7) * 16));
                    *reinterpret_cast<uint4*>(xptr + buf * X_TILE + off) = v;
                }
            }
            __syncthreads();
            (void)j0;

            const uint32_t xt = xbase + (((rloc + kh) & 3) * X_TILE);

            #pragma unroll
            for (int kw = 0; kw < 3; ++kw) {
                const int tap = kh * 3 + kw;
                const uint32_t wt_h = wbase + (tap * 2) * 8192;
                const uint32_t wt_l = wt_h + 8192;
                const int arow0 = xh64 + lrow + kw;
                const uint32_t axor = (uint32_t)((arow0 & 7) * 16);

                #pragma unroll
                for (int k = 0; k < 4; ++k) {
                    uint32_t a4[4][4];
                    #pragma unroll
                    for (int mt = 0; mt < 4; ++mt) {
                        const uint32_t ad = (uint32_t)((arow0 + 16 * mt) * 128) +
                                            (((uint32_t)(k * 32 + lcol)) ^ axor);
                        ldsm4(a4[mt], xt + ad);
                    }
                    uint32_t bb[2][4];
                    #pragma unroll
                    for (int pr = 0; pr < 2; ++pr) {
                        const uint32_t bd = (uint32_t)(((ch * 2 + pr) * 16 + lrow) * 128) +
                                            (((uint32_t)(k * 32 + lcol)) ^ bxor);
                        ldsm4(bb[pr], wt_h + bd);
                    }
                    #pragma unroll
                    for (int mt = 0; mt < 4; ++mt)
                        #pragma unroll
                        for (int pr = 0; pr < 2; ++pr) {
                            mma16816(acc[mt][pr][0], a4[mt], bb[pr][0], bb[pr][2]);
                            mma16816(acc[mt][pr][1], a4[mt], bb[pr][1], bb[pr][3]);
                        }
                    #pragma unroll
                    for (int pr = 0; pr < 2; ++pr) {
                        const uint32_t bd = (uint32_t)(((ch * 2 + pr) * 16 + lrow) * 128) +
                                            (((uint32_t)(k * 32 + lcol)) ^ bxor);
                        ldsm4(bb[pr], wt_l + bd);
                    }
                    #pragma unroll
                    for (int mt = 0; mt < 4; ++mt)
                        #pragma unroll
                        for (int pr = 0; pr < 2; ++pr) {
                            mma16816(acc[mt][pr][0], a4[mt], bb[pr][0], bb[pr][2]);
                            mma16816(acc[mt][pr][1], a4[mt], bb[pr][1], bb[pr][3]);
                        }
                }
            }
        }

        // ---- epilogue: direct float2 stores (bias + relu in regs) ----
        const int y = ty + rloc;
        #pragma unroll
        for (int mt = 0; mt < 4; ++mt) {
            const int x0 = xh64 + mt * 16 + (lane >> 2);
            #pragma unroll
            for (int pr = 0; pr < 2; ++pr)
                #pragma unroll
                for (int h = 0; h < 2; ++h) {
                    const int co = ch * 32 + pr * 16 + h * 8 + (lane & 3) * 2;
                    const float b0v = biasp[co];
                    const float b1v = biasp[co + 1];
                    float* base = out + (((size_t)b * COUT + co) * HH + y) * WW;
                    float2 v0, v1;
                    v0.x = fmaxf(acc[mt][pr][h][0] + b0v, 0.0f);
                    v0.y = fmaxf(acc[mt][pr][h][1] + b1v, 0.0f);
                    v1.x = fmaxf(acc[mt][pr][h][2] + b0v, 0.0f);
                    v1.y = fmaxf(acc[mt][pr][h][3] + b1v, 0.0f);
                    // co and co+1 are adjacent planes: store per-plane scalars
                    base[x0]            = v0.x;
                    base[WW * HH + x0]  = v0.y;
                    base[x0 + 8]        = v1.x;
                    base[WW * HH + x0 + 8] = v1.y;
                }
        }
        __syncthreads();   // acc stores done before next tile's restaging
    }
}

// ---------------------------------------------------------------------------
extern "C" void kernel_launch(void* const* d_in, const int* in_sizes, int n_in,
                              void* d_out, int out_size) {
    const float* x  = (const float*)d_in[0];
    const float* z  = (const float*)d_in[1];
    const float* W0 = (const float*)d_in[2];
    const float* b0 = (const float*)d_in[3];
    const float* W1 = (const float*)d_in[4];
    const float* b1 = (const float*)d_in[5];
    const float* W2 = (const float*)d_in[6];
    const float* b2 = (const float*)d_in[7];
    float* out = (float*)d_out;

    cudaFuncSetAttribute(conv_mma_kernel,
                         cudaFuncAttributeMaxDynamicSharedMemorySize, SM_TOTAL);

    mlp_aw_kernel<<<(AWN + 255) / 256, 256>>>(z, W0, b0, W1, b1, W2, b2);
    {
        dim3 g(HH, BB);
        pack_x_kernel<<<g, 256>>>(x);
    }
    {
        dim3 g(8, BB);
        conv_mma_kernel<<<g, 512, SM_TOTAL>>>(out);
    }
}

// round 9
// speedup vs baseline: 4.2270x; 1.1347x over previous
#include <cuda_runtime.h>
#include <cuda_fp16.h>
#include <cstdint>

// Problem constants
#define BB   16
#define CIN  64
#define COUT 64
#define HH   128
#define WW   128
#define NKW  36864
#define AWN  36928

// ---------------------------------------------------------------------------
// Device scratch (allocation-free rule)
// ---------------------------------------------------------------------------
__device__ float  g_bias[BB * COUT];
__device__ __half g_xh[BB * HH * WW * CIN];   // NHWC hi split
__device__ __half g_wh[BB * 9 * COUT * CIN];  // [b][tap][co][ci] hi
__device__ __half g_wl[BB * 9 * COUT * CIN];  // lo

// ---------------------------------------------------------------------------
// Helpers (family-agnostic: ldmatrix + mma.sync + cp.async, sm_80+)
// ---------------------------------------------------------------------------
__device__ __forceinline__ uint32_t smem_u32(const void* p) {
    uint32_t a;
    asm("{ .reg .u64 t; cvta.to.shared.u64 t, %1; cvt.u32.u64 %0, t; }" : "=r"(a) : "l"(p));
    return a;
}
__device__ __forceinline__ void ldsm4(uint32_t (&r)[4], uint32_t addr) {
    asm volatile("ldmatrix.sync.aligned.m8n8.x4.shared.b16 {%0,%1,%2,%3}, [%4];"
                 : "=r"(r[0]), "=r"(r[1]), "=r"(r[2]), "=r"(r[3]) : "r"(addr));
}
__device__ __forceinline__ void mma16816(float (&d)[4], const uint32_t (&a)[4],
                                         uint32_t b0, uint32_t b1) {
    asm volatile(
        "mma.sync.aligned.m16n8k16.row.col.f32.f16.f16.f32 "
        "{%0,%1,%2,%3}, {%4,%5,%6,%7}, {%8,%9}, {%0,%1,%2,%3};"
        : "+f"(d[0]), "+f"(d[1]), "+f"(d[2]), "+f"(d[3])
        : "r"(a[0]), "r"(a[1]), "r"(a[2]), "r"(a[3]), "r"(b0), "r"(b1));
}
__device__ __forceinline__ void cp16(uint32_t dst, const void* src, int sz) {
    asm volatile("cp.async.cg.shared.global [%0], [%1], 16, %2;"
                 :: "r"(dst), "l"(src), "r"(sz) : "memory");
}
#define CP_COMMIT() asm volatile("cp.async.commit_group;" ::: "memory")
#define CP_WAIT0()  asm volatile("cp.async.wait_group 0;" ::: "memory")

// ---------------------------------------------------------------------------
// Fused MLP + weight pack: h -> aw -> {g_wh, g_wl, g_bias} directly.
// ---------------------------------------------------------------------------
__global__ __launch_bounds__(256) void mlp_aw_kernel(const float* __restrict__ z,
                                                     const float* __restrict__ W0,
                                                     const float* __restrict__ b0,
                                                     const float* __restrict__ W1,
                                                     const float* __restrict__ b1,
                                                     const float* __restrict__ W2,
                                                     const float* __restrict__ b2) {
    __shared__ float sz[BB * 16];
    __shared__ float h0[BB * 20];
    __shared__ float sh[BB * 30];
    const int tid = threadIdx.x;

    sz[tid] = z[tid];
    __syncthreads();
    for (int e = tid; e < BB * 20; e += 256) {
        const int b = e / 20, u = e % 20;
        float s = b0[u];
        #pragma unroll
        for (int j = 0; j < 16; ++j) s += sz[b * 16 + j] * W0[u * 16 + j];
        h0[e] = fmaxf(s, 0.0f);
    }
    __syncthreads();
    for (int e = tid; e < BB * 30; e += 256) {
        const int b = e / 30, u = e % 30;
        float s = b1[u];
        #pragma unroll
        for (int j = 0; j < 20; ++j) s += h0[b * 20 + j] * W1[u * 20 + j];
        sh[e] = fmaxf(s, 0.0f);
    }
    __syncthreads();

    const int i = blockIdx.x * 256 + tid;
    if (i >= AWN) return;
    float w[30];
    #pragma unroll
    for (int j = 0; j < 30; ++j) w[j] = W2[i * 30 + j];
    const float bias = b2[i];

    if (i < NKW) {
        const int co  = i / 576;
        const int rem = i % 576;
        const int ci  = rem / 9;
        const int s9  = rem % 9;
        #pragma unroll
        for (int b = 0; b < BB; ++b) {
            float s = bias;
            #pragma unroll
            for (int j = 0; j < 30; ++j) s += sh[b * 30 + j] * w[j];
            const float v = fmaxf(s, 0.0f);
            const __half hi = __float2half_rn(v);
            const float lo = v - __half2float(hi);
            const size_t o = ((size_t)(b * 9 + s9) * 64 + co) * 64 + ci;
            g_wh[o] = hi;
            g_wl[o] = __float2half_rn(lo);
        }
    } else {
        const int co = i - NKW;
        #pragma unroll
        for (int b = 0; b < BB; ++b) {
            float s = bias;
            #pragma unroll
            for (int j = 0; j < 30; ++j) s += sh[b * 30 + j] * w[j];
            g_bias[b * 64 + co] = fmaxf(s, 0.0f);
        }
    }
}

// ---------------------------------------------------------------------------
// Pack x: NCHW f32 -> NHWC fp16 hi (smem transpose, coalesced both sides)
// ---------------------------------------------------------------------------
__global__ __launch_bounds__(256) void pack_x_kernel(const float* __restrict__ x) {
    __shared__ float s[64][129];
    const int b = blockIdx.y;
    const int y = blockIdx.x;
    const int tid = threadIdx.x;
    const int px = tid & 127, hh = tid >> 7;
    #pragma unroll
    for (int it = 0; it < 32; ++it) {
        const int ci = it * 2 + hh;
        s[ci][px] = x[((size_t)(b * 64 + ci) * HH + y) * WW + px];
    }
    __syncthreads();
    const int ci2 = tid & 63, pg = tid >> 6;
    #pragma unroll
    for (int it = 0; it < 32; ++it) {
        const int p2 = it * 4 + pg;
        g_xh[((size_t)(b * HH + y) * WW + p2) * 64 + ci2] =
            __float2half_rn(s[ci2][p2]);
    }
}

// ---------------------------------------------------------------------------
// Conv, persistent-slab, rolling 5-slot x ring + cp.async pipelining.
// Grid: (8 slabs, 16 batch), 512 threads, 4 tiles of 4 output rows each.
// Warp = 64 px x 32 co (mt=4, pr=2). Weights (144KB) resident.
// Ring: slot(row) = (row+1) % 5. Steady state: 4 new rows/tile; 3 of 4
// loads overlap with MMA (slot-safety verified per phase).
// ---------------------------------------------------------------------------
#define W_SMEM  147456
#define X_TILE  16640                       // 130 rows * 128B
#define NSLOT   5
#define SM_TOTAL (W_SMEM + NSLOT * X_TILE)  // 230656

__global__ __launch_bounds__(512, 1) void conv_mma_kernel(float* __restrict__ out) {
    extern __shared__ char smem[];
    char* wptr = smem;
    char* xptr = smem + W_SMEM;
    const uint32_t wbase = smem_u32(wptr);
    const uint32_t xbase = smem_u32(xptr);

    const int tid  = threadIdx.x;
    const int wid  = tid >> 5;
    const int lane = tid & 31;
    const int slab = blockIdx.x;            // 0..7
    const int b    = blockIdx.y;
    const int ty0  = slab * 16;

    // ---- row stager: one image row -> ring slot, zero-fill OOB ----
    auto stage_row = [&](int rowimg) {
        const uint32_t slot = (uint32_t)((rowimg + 1) % NSLOT);
        const uint32_t sdst = xbase + slot * X_TILE;
        const int rc = min(max(rowimg, 0), HH - 1);
        for (int e = tid; e < 1040; e += 512) {
            const int r  = e >> 3;
            const int c  = e & 7;
            const int px = r - 1;
            const int pc = min(max(px, 0), WW - 1);
            const int sz = ((unsigned)rowimg < (unsigned)HH &&
                            (unsigned)px < (unsigned)WW) ? 16 : 0;
            const __half* src = g_xh + (((size_t)(b * HH + rc) * WW + pc) * 64 + c * 8);
            const uint32_t off = r * 128 + ((c * 16) ^ ((r & 7) * 16));
            cp16(sdst + off, src, sz);
        }
        CP_COMMIT();
    };

    // ---- stage ALL weights once (9 taps, hi+lo), swizzled [row=co][128B] ----
    for (int e = tid; e < 9216; e += 512) {
        const int chunk = e & 7;
        const int co    = (e >> 3) & 63;
        const int split = (e >> 9) & 1;
        const int tap   = e >> 10;
        const __half* src = (split ? g_wl : g_wh) +
            (((size_t)(b * 9 + tap) * 64 + co) * 64 + chunk * 8);
        const uint32_t off = co * 128 + ((chunk * 16) ^ ((co & 7) * 16));
        *reinterpret_cast<uint4*>(wptr + (tap * 2 + split) * 8192 + off) =
            *reinterpret_cast<const uint4*>(src);
    }

    // prologue: rows ty0-1, ty0, ty0+1 in flight
    stage_row(ty0 - 1);
    stage_row(ty0);
    stage_row(ty0 + 1);

    // ---- per-warp geometry: 16 warps = mq(8) x ch(2); warp = 64px x 32co ----
    const int mq   = wid >> 1;
    const int ch   = wid & 1;
    const int rloc = mq >> 1;               // local output row 0..3
    const int xh64 = (mq & 1) * 64;
    const int lrow = lane & 15;
    const int lcol = (lane >> 4) * 16;
    const uint32_t bxor = (uint32_t)((lane & 7) * 16);

    const float* biasp = g_bias + b * 64;

    for (int tile = 0; tile < 4; ++tile) {
        const int ty = ty0 + tile * 4;

        float acc[4][2][2][4];
        #pragma unroll
        for (int mt = 0; mt < 4; ++mt)
            #pragma unroll
            for (int pr = 0; pr < 2; ++pr)
                #pragma unroll
                for (int h = 0; h < 2; ++h)
                    #pragma unroll
                    for (int q = 0; q < 4; ++q) acc[mt][pr][h][q] = 0.0f;

        #pragma unroll 1
        for (int kh = 0; kh < 3; ++kh) {
            // kh0: top row (ty+2) staged synchronously (its slot was read last tile)
            if (kh == 0) stage_row(ty + 2);
            CP_WAIT0();
            __syncthreads();
            // prefetch one row ahead, into the slot NOT read this phase
            const int pre = ty + 3 + kh;    // kh0->ty+3, kh1->ty+4, kh2->ty+5
            if (pre <= ty0 + 16) stage_row(pre);

            // my A row this phase: image row (ty + rloc + kh - 1)
            const uint32_t xt = xbase +
                (uint32_t)(((ty + rloc + kh) % NSLOT)) * X_TILE;   // (row+1)%5

            #pragma unroll
            for (int kw = 0; kw < 3; ++kw) {
                const int tap = kh * 3 + kw;
                const uint32_t wt_h = wbase + (tap * 2) * 8192;
                const uint32_t wt_l = wt_h + 8192;
                const int arow0 = xh64 + lrow + kw;
                const uint32_t axor = (uint32_t)((arow0 & 7) * 16);

                #pragma unroll
                for (int k = 0; k < 4; ++k) {
                    uint32_t a4[4][4];
                    #pragma unroll
                    for (int mt = 0; mt < 4; ++mt) {
                        const uint32_t ad = (uint32_t)((arow0 + 16 * mt) * 128) +
                                            (((uint32_t)(k * 32 + lcol)) ^ axor);
                        ldsm4(a4[mt], xt + ad);
                    }
                    uint32_t bb[2][4];
                    #pragma unroll
                    for (int pr = 0; pr < 2; ++pr) {
                        const uint32_t bd = (uint32_t)(((ch * 2 + pr) * 16 + lrow) * 128) +
                                            (((uint32_t)(k * 32 + lcol)) ^ bxor);
                        ldsm4(bb[pr], wt_h + bd);
                    }
                    #pragma unroll
                    for (int mt = 0; mt < 4; ++mt)
                        #pragma unroll
                        for (int pr = 0; pr < 2; ++pr) {
                            mma16816(acc[mt][pr][0], a4[mt], bb[pr][0], bb[pr][2]);
                            mma16816(acc[mt][pr][1], a4[mt], bb[pr][1], bb[pr][3]);
                        }
                    #pragma unroll
                    for (int pr = 0; pr < 2; ++pr) {
                        const uint32_t bd = (uint32_t)(((ch * 2 + pr) * 16 + lrow) * 128) +
                                            (((uint32_t)(k * 32 + lcol)) ^ bxor);
                        ldsm4(bb[pr], wt_l + bd);
                    }
                    #pragma unroll
                    for (int mt = 0; mt < 4; ++mt)
                        #pragma unroll
                        for (int pr = 0; pr < 2; ++pr) {
                            mma16816(acc[mt][pr][0], a4[mt], bb[pr][0], bb[pr][2]);
                            mma16816(acc[mt][pr][1], a4[mt], bb[pr][1], bb[pr][3]);
                        }
                }
            }
        }

        // ---- epilogue: direct stores (bias + relu in regs), no smem use ----
        const int y = ty + rloc;
        #pragma unroll
        for (int mt = 0; mt < 4; ++mt) {
            const int x0 = xh64 + mt * 16 + (lane >> 2);
            #pragma unroll
            for (int pr = 0; pr < 2; ++pr)
                #pragma unroll
                for (int h = 0; h < 2; ++h) {
                    const int co = ch * 32 + pr * 16 + h * 8 + (lane & 3) * 2;
                    const float b0v = biasp[co];
                    const float b1v = biasp[co + 1];
                    float* base = out + (((size_t)b * COUT + co) * HH + y) * WW;
                    base[x0]               = fmaxf(acc[mt][pr][h][0] + b0v, 0.0f);
                    base[WW * HH + x0]     = fmaxf(acc[mt][pr][h][1] + b1v, 0.0f);
                    base[x0 + 8]           = fmaxf(acc[mt][pr][h][2] + b0v, 0.0f);
                    base[WW * HH + x0 + 8] = fmaxf(acc[mt][pr][h][3] + b1v, 0.0f);
                }
        }
        __syncthreads();   // all phases' reads done before next tile overwrites ring
    }
}

// ---------------------------------------------------------------------------
extern "C" void kernel_launch(void* const* d_in, const int* in_sizes, int n_in,
                              void* d_out, int out_size) {
    const float* x  = (const float*)d_in[0];
    const float* z  = (const float*)d_in[1];
    const float* W0 = (const float*)d_in[2];
    const float* b0 = (const float*)d_in[3];
    const float* W1 = (const float*)d_in[4];
    const float* b1 = (const float*)d_in[5];
    const float* W2 = (const float*)d_in[6];
    const float* b2 = (const float*)d_in[7];
    float* out = (float*)d_out;

    cudaFuncSetAttribute(conv_mma_kernel,
                         cudaFuncAttributeMaxDynamicSharedMemorySize, SM_TOTAL);

    mlp_aw_kernel<<<(AWN + 255) / 256, 256>>>(z, W0, b0, W1, b1, W2, b2);
    {
        dim3 g(HH, BB);
        pack_x_kernel<<<g, 256>>>(x);
    }
    {
        dim3 g(8, BB);
        conv_mma_kernel<<<g, 512, SM_TOTAL>>>(out);
    }
}

// round 11
// speedup vs baseline: 6.2418x; 1.4766x over previous
#include <cuda_runtime.h>
#include <cuda_fp16.h>
#include <cstdint>

// Problem constants
#define BB   16
#define CIN  64
#define COUT 64
#define HH   128
#define WW   128
#define NKW  36864
#define AWN  36928

// ---------------------------------------------------------------------------
// Device scratch (allocation-free rule)
// ---------------------------------------------------------------------------
__device__ float  g_bias[BB * COUT];
__device__ __half g_xh[BB * HH * WW * CIN];   // NHWC fp16
__device__ __half g_wh[BB * 9 * COUT * CIN];  // [b][tap][co][ci] fp16

// ---------------------------------------------------------------------------
// Helpers (family-agnostic: ldmatrix + mma.sync + cp.async, sm_80+)
// ---------------------------------------------------------------------------
__device__ __forceinline__ uint32_t smem_u32(const void* p) {
    uint32_t a;
    asm("{ .reg .u64 t; cvta.to.shared.u64 t, %1; cvt.u32.u64 %0, t; }" : "=r"(a) : "l"(p));
    return a;
}
__device__ __forceinline__ void ldsm4(uint32_t (&r)[4], uint32_t addr) {
    asm volatile("ldmatrix.sync.aligned.m8n8.x4.shared.b16 {%0,%1,%2,%3}, [%4];"
                 : "=r"(r[0]), "=r"(r[1]), "=r"(r[2]), "=r"(r[3]) : "r"(addr));
}
__device__ __forceinline__ void mma16816(float (&d)[4], const uint32_t (&a)[4],
                                         uint32_t b0, uint32_t b1) {
    asm volatile(
        "mma.sync.aligned.m16n8k16.row.col.f32.f16.f16.f32 "
        "{%0,%1,%2,%3}, {%4,%5,%6,%7}, {%8,%9}, {%0,%1,%2,%3};"
        : "+f"(d[0]), "+f"(d[1]), "+f"(d[2]), "+f"(d[3])
        : "r"(a[0]), "r"(a[1]), "r"(a[2]), "r"(a[3]), "r"(b0), "r"(b1));
}
__device__ __forceinline__ void cp16(uint32_t dst, const void* src, int sz) {
    asm volatile("cp.async.cg.shared.global [%0], [%1], 16, %2;"
                 :: "r"(dst), "l"(src), "r"(sz) : "memory");
}
#define CP_COMMIT() asm volatile("cp.async.commit_group;" ::: "memory")
#define CP_WAIT0()  asm volatile("cp.async.wait_group 0;" ::: "memory")

// ---------------------------------------------------------------------------
// Fused MLP + weight pack: h -> aw -> {g_wh, g_bias} directly.
// ---------------------------------------------------------------------------
__global__ __launch_bounds__(256) void mlp_aw_kernel(const float* __restrict__ z,
                                                     const float* __restrict__ W0,
                                                     const float* __restrict__ b0,
                                                     const float* __restrict__ W1,
                                                     const float* __restrict__ b1,
                                                     const float* __restrict__ W2,
                                                     const float* __restrict__ b2) {
    __shared__ float sz[BB * 16];
    __shared__ float h0[BB * 20];
    __shared__ float sh[BB * 30];
    const int tid = threadIdx.x;

    sz[tid] = z[tid];
    __syncthreads();
    for (int e = tid; e < BB * 20; e += 256) {
        const int b = e / 20, u = e % 20;
        float s = b0[u];
        #pragma unroll
        for (int j = 0; j < 16; ++j) s += sz[b * 16 + j] * W0[u * 16 + j];
        h0[e] = fmaxf(s, 0.0f);
    }
    __syncthreads();
    for (int e = tid; e < BB * 30; e += 256) {
        const int b = e / 30, u = e % 30;
        float s = b1[u];
        #pragma unroll
        for (int j = 0; j < 20; ++j) s += h0[b * 20 + j] * W1[u * 20 + j];
        sh[e] = fmaxf(s, 0.0f);
    }
    __syncthreads();

    const int i = blockIdx.x * 256 + tid;
    if (i >= AWN) return;
    float w[30];
    #pragma unroll
    for (int j = 0; j < 30; ++j) w[j] = W2[i * 30 + j];
    const float bias = b2[i];

    if (i < NKW) {
        const int co  = i / 576;
        const int rem = i % 576;
        const int ci  = rem / 9;
        const int s9  = rem % 9;
        #pragma unroll
        for (int b = 0; b < BB; ++b) {
            float s = bias;
            #pragma unroll
            for (int j = 0; j < 30; ++j) s += sh[b * 30 + j] * w[j];
            g_wh[((size_t)(b * 9 + s9) * 64 + co) * 64 + ci] =
                __float2half_rn(fmaxf(s, 0.0f));
        }
    } else {
        const int co = i - NKW;
        #pragma unroll
        for (int b = 0; b < BB; ++b) {
            float s = bias;
            #pragma unroll
            for (int j = 0; j < 30; ++j) s += sh[b * 30 + j] * w[j];
            g_bias[b * 64 + co] = fmaxf(s, 0.0f);
        }
    }
}

// ---------------------------------------------------------------------------
// Pack x: NCHW f32 -> NHWC fp16 (smem transpose, coalesced both sides)
// ---------------------------------------------------------------------------
__global__ __launch_bounds__(256) void pack_x_kernel(const float* __restrict__ x) {
    __shared__ float s[64][129];
    const int b = blockIdx.y;
    const int y = blockIdx.x;
    const int tid = threadIdx.x;
    const int px = tid & 127, hh = tid >> 7;
    #pragma unroll
    for (int it = 0; it < 32; ++it) {
        const int ci = it * 2 + hh;
        s[ci][px] = x[((size_t)(b * 64 + ci) * HH + y) * WW + px];
    }
    __syncthreads();
    const int ci2 = tid & 63, pg = tid >> 6;
    #pragma unroll
    for (int it = 0; it < 32; ++it) {
        const int p2 = it * 4 + pg;
        g_xh[((size_t)(b * HH + y) * WW + p2) * 64 + ci2] =
            __float2half_rn(s[ci2][p2]);
    }
}

// ---------------------------------------------------------------------------
// Conv, persistent-slab, rolling 5-slot x ring + cp.async, single fp16 pass.
// Grid: (8 slabs, 16 batch), 512 threads, 4 tiles of 4 output rows each.
// Warp = 64 px x 32 co (mt=4, pr=2). Weights (72KB, 9 taps) resident.
// Per k-step: 6 LDSM.x4 / 16 MMA.
// ---------------------------------------------------------------------------
#define W_SMEM  73728                       // 9 taps * 8KB
#define X_TILE  16640                       // 130 rows * 128B
#define NSLOT   5
#define SM_TOTAL (W_SMEM + NSLOT * X_TILE)  // 156928

__global__ __launch_bounds__(512, 1) void conv_mma_kernel(float* __restrict__ out) {
    extern __shared__ char smem[];
    char* wptr = smem;
    char* xptr = smem + W_SMEM;
    const uint32_t wbase = smem_u32(wptr);
    const uint32_t xbase = smem_u32(xptr);

    const int tid  = threadIdx.x;
    const int wid  = tid >> 5;
    const int lane = tid & 31;
    const int slab = blockIdx.x;            // 0..7
    const int b    = blockIdx.y;
    const int ty0  = slab * 16;

    // ---- row stager: one image row -> ring slot, zero-fill OOB ----
    auto stage_row = [&](int rowimg) {
        const uint32_t slot = (uint32_t)((rowimg + 1) % NSLOT);
        const uint32_t sdst = xbase + slot * X_TILE;
        const int rc = min(max(rowimg, 0), HH - 1);
        for (int e = tid; e < 1040; e += 512) {
            const int r  = e >> 3;
            const int c  = e & 7;
            const int px = r - 1;
            const int pc = min(max(px, 0), WW - 1);
            const int sz = ((unsigned)rowimg < (unsigned)HH &&
                            (unsigned)px < (unsigned)WW) ? 16 : 0;
            const __half* src = g_xh + (((size_t)(b * HH + rc) * WW + pc) * 64 + c * 8);
            const uint32_t off = r * 128 + ((c * 16) ^ ((r & 7) * 16));
            cp16(sdst + off, src, sz);
        }
        CP_COMMIT();
    };

    // ---- stage ALL weights once (9 taps), swizzled [row=co][128B] ----
    for (int e = tid; e < 4608; e += 512) {
        const int chunk = e & 7;
        const int co    = (e >> 3) & 63;
        const int tap   = e >> 9;
        const __half* src = g_wh +
            (((size_t)(b * 9 + tap) * 64 + co) * 64 + chunk * 8);
        const uint32_t off = co * 128 + ((chunk * 16) ^ ((co & 7) * 16));
        *reinterpret_cast<uint4*>(wptr + tap * 8192 + off) =
            *reinterpret_cast<const uint4*>(src);
    }

    // prologue: rows ty0-1, ty0, ty0+1 in flight
    stage_row(ty0 - 1);
    stage_row(ty0);
    stage_row(ty0 + 1);

    // ---- per-warp geometry: 16 warps = mq(8) x ch(2); warp = 64px x 32co ----
    const int mq   = wid >> 1;
    const int ch   = wid & 1;
    const int rloc = mq >> 1;               // local output row 0..3
    const int xh64 = (mq & 1) * 64;
    const int lrow = lane & 15;
    const int lcol = (lane >> 4) * 16;
    const uint32_t bxor = (uint32_t)((lane & 7) * 16);

    const float* biasp = g_bias + b * 64;

    for (int tile = 0; tile < 4; ++tile) {
        const int ty = ty0 + tile * 4;

        float acc[4][2][2][4];
        #pragma unroll
        for (int mt = 0; mt < 4; ++mt)
            #pragma unroll
            for (int pr = 0; pr < 2; ++pr)
                #pragma unroll
                for (int h = 0; h < 2; ++h)
                    #pragma unroll
                    for (int q = 0; q < 4; ++q) acc[mt][pr][h][q] = 0.0f;

        #pragma unroll 1
        for (int kh = 0; kh < 3; ++kh) {
            // kh0: top row (ty+2) staged synchronously (its slot was read last tile)
            if (kh == 0) stage_row(ty + 2);
            CP_WAIT0();
            __syncthreads();
            // prefetch one row ahead, into the slot NOT read this phase
            const int pre = ty + 3 + kh;    // kh0->ty+3, kh1->ty+4, kh2->ty+5
            if (pre <= ty0 + 16) stage_row(pre);

            const uint32_t xt = xbase +
                (uint32_t)(((ty + rloc + kh) % NSLOT)) * X_TILE;   // (row+1)%5

            #pragma unroll
            for (int kw = 0; kw < 3; ++kw) {
                const int tap = kh * 3 + kw;
                const uint32_t wt = wbase + tap * 8192;
                const int arow0 = xh64 + lrow + kw;
                const uint32_t axor = (uint32_t)((arow0 & 7) * 16);

                #pragma unroll
                for (int k = 0; k < 4; ++k) {
                    uint32_t a4[4][4];
                    #pragma unroll
                    for (int mt = 0; mt < 4; ++mt) {
                        const uint32_t ad = (uint32_t)((arow0 + 16 * mt) * 128) +
                                            (((uint32_t)(k * 32 + lcol)) ^ axor);
                        ldsm4(a4[mt], xt + ad);
                    }
                    uint32_t bb[2][4];
                    #pragma unroll
                    for (int pr = 0; pr < 2; ++pr) {
                        const uint32_t bd = (uint32_t)(((ch * 2 + pr) * 16 + lrow) * 128) +
                                            (((uint32_t)(k * 32 + lcol)) ^ bxor);
                        ldsm4(bb[pr], wt + bd);
                    }
                    #pragma unroll
                    for (int mt = 0; mt < 4; ++mt)
                        #pragma unroll
                        for (int pr = 0; pr < 2; ++pr) {
                            mma16816(acc[mt][pr][0], a4[mt], bb[pr][0], bb[pr][2]);
                            mma16816(acc[mt][pr][1], a4[mt], bb[pr][1], bb[pr][3]);
                        }
                }
            }
        }

        // ---- epilogue: direct stores (bias + relu in regs) ----
        const int y = ty + rloc;
        #pragma unroll
        for (int mt = 0; mt < 4; ++mt) {
            const int x0 = xh64 + mt * 16 + (lane >> 2);
            #pragma unroll
            for (int pr = 0; pr < 2; ++pr)
                #pragma unroll
                for (int h = 0; h < 2; ++h) {
                    const int co = ch * 32 + pr * 16 + h * 8 + (lane & 3) * 2;
                    const float b0v = biasp[co];
                    const float b1v = biasp[co + 1];
                    float* base = out + (((size_t)b * COUT + co) * HH + y) * WW;
                    base[x0]               = fmaxf(acc[mt][pr][h][0] + b0v, 0.0f);
                    base[WW * HH + x0]     = fmaxf(acc[mt][pr][h][1] + b1v, 0.0f);
                    base[x0 + 8]           = fmaxf(acc[mt][pr][h][2] + b0v, 0.0f);
                    base[WW * HH + x0 + 8] = fmaxf(acc[mt][pr][h][3] + b1v, 0.0f);
                }
        }
        __syncthreads();   // all phases' reads done before next tile overwrites ring
    }
}

// ---------------------------------------------------------------------------
extern "C" void kernel_launch(void* const* d_in, const int* in_sizes, int n_in,
                              void* d_out, int out_size) {
    const float* x  = (const float*)d_in[0];
    const float* z  = (const float*)d_in[1];
    const float* W0 = (const float*)d_in[2];
    const float* b0 = (const float*)d_in[3];
    const float* W1 = (const float*)d_in[4];
    const float* b1 = (const float*)d_in[5];
    const float* W2 = (const float*)d_in[6];
    const float* b2 = (const float*)d_in[7];
    float* out = (float*)d_out;

    cudaFuncSetAttribute(conv_mma_kernel,
                         cudaFuncAttributeMaxDynamicSharedMemorySize, SM_TOTAL);

    mlp_aw_kernel<<<(AWN + 255) / 256, 256>>>(z, W0, b0, W1, b1, W2, b2);
    {
        dim3 g(HH, BB);
        pack_x_kernel<<<g, 256>>>(x);
    }
    {
        dim3 g(8, BB);
        conv_mma_kernel<<<g, 512, SM_TOTAL>>>(out);
    }
}